// round 2
// baseline (speedup 1.0000x reference)
#include <cuda_runtime.h>
#include <math.h>

#define NN    6912                 // nodes
#define NE    82944                // edges (no self loops)
#define NE2   89856                // edges + self loops
#define DV    96                   // per-node feature width
#define TOT   (NN*DV)              // 663552 output elements
#define HIDW  384

// ---------------- scratch (static device globals; no allocs) ----------------
__device__ __align__(128) float g_hA[NN*HIDW];
__device__ __align__(128) float g_hB[NN*HIDW];
__device__ __align__(128) float g_res[TOT];
__device__ __align__(128) float g_xl[NN*HIDW];
__device__ __align__(128) float g_xr[NN*HIDW];
__device__ __align__(128) float g_logits[NE2*4];
__device__ int    g_off[NN+1];
__device__ int    g_cur[NN];
__device__ int    g_deg[NN];
__device__ int    g_csrc[NE2];
__device__ int    g_cdst[NE2];
__device__ double g_stat[2];

// ---------------- init: self-loop degree=1, zero LN accumulators ------------
__global__ void k_init() {
    int i = blockIdx.x*blockDim.x + threadIdx.x;
    if (i < NN) g_deg[i] = 1;
    if (i == 0) { g_stat[0] = 0.0; g_stat[1] = 0.0; }
}

// h0 = concat(x, repeat(circ_feat, Q)); also save residual
__global__ void k_build_h0(const float* __restrict__ x, const float* __restrict__ cf) {
    int i = blockIdx.x*blockDim.x + threadIdx.x;
    if (i >= TOT) return;
    int row = i / DV;
    int col = i - row*DV;
    float v;
    if (col < 32) v = x[row*32 + col];
    else          v = cf[(row/27)*64 + (col - 32)];
    g_hA[i]  = v;
    g_res[i] = v;
}

__global__ void k_count(const int* __restrict__ ei) {
    int e = blockIdx.x*blockDim.x + threadIdx.x;
    if (e < NE) atomicAdd(&g_deg[ei[NE + e]], 1);
}

// single-block exclusive scan over degrees -> CSR offsets + cursors
__global__ void k_scan() {
    __shared__ int s[1024];
    int tid = threadIdx.x;
    int carry = 0;
    for (int c0 = 0; c0 < NN; c0 += 1024) {
        int i = c0 + tid;
        int v = (i < NN) ? g_deg[i] : 0;
        s[tid] = v;
        __syncthreads();
        for (int o = 1; o < 1024; o <<= 1) {
            int t = (tid >= o) ? s[tid - o] : 0;
            __syncthreads();
            s[tid] += t;
            __syncthreads();
        }
        int incl = s[tid];
        if (i < NN) { int ex = carry + incl - v; g_off[i] = ex; g_cur[i] = ex; }
        int total = s[1023];
        __syncthreads();
        carry += total;
    }
    if (tid == 0) g_off[NN] = carry;
}

__global__ void k_scatter(const int* __restrict__ ei) {
    int i = blockIdx.x*blockDim.x + threadIdx.x;
    if (i >= NE2) return;
    int s, d;
    if (i < NE) { s = ei[i]; d = ei[NE + i]; }
    else        { s = i - NE; d = s; }
    int pos = atomicAdd(&g_cur[d], 1);
    g_csrc[pos] = s;
    g_cdst[pos] = d;
}

// ---------------- fp32 GEMM: C[M,Nc] = A[M,K] @ B[K,Nc]; M=NN -------------
// 128x64 tile, BK=8, 256 threads, 8x4 per thread.
__global__ void __launch_bounds__(256) k_gemm(const float* __restrict__ A,
        const float* __restrict__ B, float* __restrict__ C, int K, int Nc) {
    __shared__ float As[8][128];
    __shared__ float Bs[8][64];
    int tid = threadIdx.x;
    int tx = tid & 15, ty = tid >> 4;
    int ar = tid >> 1, akq = tid & 1;     // A tile: row, float4-in-k
    int bkr = tid >> 4, bcq = tid & 15;   // B tile (tid<128): k-row, float4-in-n
    int bcol = blockIdx.x*64 + bcq*4;
    const float* Ap = A + (size_t)(blockIdx.y*128 + ar)*K + akq*4;

    float acc[8][4];
    #pragma unroll
    for (int i = 0; i < 8; i++)
        #pragma unroll
        for (int j = 0; j < 4; j++) acc[i][j] = 0.f;

    for (int k0 = 0; k0 < K; k0 += 8) {
        float4 av = *(const float4*)(Ap + k0);
        As[akq*4+0][ar] = av.x;
        As[akq*4+1][ar] = av.y;
        As[akq*4+2][ar] = av.z;
        As[akq*4+3][ar] = av.w;
        if (tid < 128) {
            float4 bv = make_float4(0.f, 0.f, 0.f, 0.f);
            if (bcol < Nc) bv = *(const float4*)(B + (size_t)(k0 + bkr)*Nc + bcol);
            Bs[bkr][bcq*4+0] = bv.x;
            Bs[bkr][bcq*4+1] = bv.y;
            Bs[bkr][bcq*4+2] = bv.z;
            Bs[bkr][bcq*4+3] = bv.w;
        }
        __syncthreads();
        #pragma unroll
        for (int k = 0; k < 8; k++) {
            float bq[4];
            #pragma unroll
            for (int j = 0; j < 4; j++) bq[j] = Bs[k][tx*4 + j];
            #pragma unroll
            for (int i = 0; i < 8; i++) {
                float a = As[k][ty*8 + i];
                #pragma unroll
                for (int j = 0; j < 4; j++) acc[i][j] = fmaf(a, bq[j], acc[i][j]);
            }
        }
        __syncthreads();
    }
    int crow = blockIdx.y*128 + ty*8;
    int ccol = blockIdx.x*64 + tx*4;
    #pragma unroll
    for (int i = 0; i < 8; i++)
        #pragma unroll
        for (int j = 0; j < 4; j++)
            if (ccol + j < Nc) C[(size_t)(crow + i)*Nc + ccol + j] = acc[i][j];
}

// ---------------- per-edge attention logits (warp per CSR position) ---------
__global__ void k_logits(const float* __restrict__ xl, const float* __restrict__ xr,
        const float* __restrict__ att, int H) {
    int p = (blockIdx.x*blockDim.x + threadIdx.x) >> 5;
    if (p >= NE2) return;
    int lane = threadIdx.x & 31;
    int W = H * 96;
    const float* ps = xl + (size_t)g_csrc[p]*W;
    const float* pd = xr + (size_t)g_cdst[p]*W;
    for (int h = 0; h < H; h++) {
        float acc = 0.f;
        #pragma unroll
        for (int j = 0; j < 3; j++) {
            int c = h*96 + lane + j*32;
            float v = ps[c] + pd[c];
            v = v > 0.f ? v : 0.2f*v;
            acc = fmaf(__ldg(att + h*96 + lane + j*32), v, acc);
        }
        #pragma unroll
        for (int o = 16; o; o >>= 1) acc += __shfl_xor_sync(0xffffffffu, acc, o);
        if (lane == 0) g_logits[(size_t)p*H + h] = acc;
    }
}

// ---------------- per-dst softmax + aggregation (block per node) ------------
// blockDim = H*96. Bias + outer leaky_relu(0.01) fused in.
__global__ void k_agg(const float* __restrict__ xl, const float* __restrict__ bias,
        float* __restrict__ out, int H) {
    int b   = blockIdx.x;
    int tid = threadIdx.x;
    int W   = blockDim.x;            // H*96
    int h   = tid / 96;
    int lane = tid & 31, wid = tid >> 5;
    int e0 = g_off[b], deg = g_off[b+1] - e0;

    __shared__ float s_m[4], s_id[4];
    if (wid < H) {
        float m = -1e30f;
        for (int i = lane; i < deg; i += 32)
            m = fmaxf(m, g_logits[(size_t)(e0+i)*H + wid]);
        #pragma unroll
        for (int o = 16; o; o >>= 1) m = fmaxf(m, __shfl_xor_sync(0xffffffffu, m, o));
        float ss = 0.f;
        for (int i = lane; i < deg; i += 32)
            ss += __expf(g_logits[(size_t)(e0+i)*H + wid] - m);
        #pragma unroll
        for (int o = 16; o; o >>= 1) ss += __shfl_xor_sync(0xffffffffu, ss, o);
        if (lane == 0) { s_m[wid] = m; s_id[wid] = 1.f/ss; }
    }
    __syncthreads();

    __shared__ float s_alpha[4*96];
    __shared__ int   s_src[96];
    float a0 = 0.f, a1 = 0.f;
    for (int base = 0; base < deg; base += 96) {
        int cn = min(96, deg - base);
        if (tid < cn) s_src[tid] = g_csrc[e0 + base + tid];
        if (wid < H) {
            float m = s_m[wid], id = s_id[wid];
            for (int i = lane; i < cn; i += 32)
                s_alpha[wid*96 + i] =
                    __expf(g_logits[(size_t)(e0 + base + i)*H + wid] - m) * id;
        }
        __syncthreads();
        int i = 0;
        for (; i + 2 <= cn; i += 2) {
            a0 = fmaf(s_alpha[h*96 + i],     xl[(size_t)s_src[i]  *W + tid], a0);
            a1 = fmaf(s_alpha[h*96 + i + 1], xl[(size_t)s_src[i+1]*W + tid], a1);
        }
        if (i < cn) a0 = fmaf(s_alpha[h*96 + i], xl[(size_t)s_src[i]*W + tid], a0);
        __syncthreads();
    }
    float o = a0 + a1 + bias[tid];
    out[(size_t)b*W + tid] = o > 0.f ? o : 0.01f*o;
}

// ---------------- residual add + LN statistics ------------------------------
__global__ void k_resred(const float* __restrict__ h5, float* __restrict__ buf) {
    double s = 0.0, s2 = 0.0;
    for (int i = blockIdx.x*blockDim.x + threadIdx.x; i < TOT;
         i += gridDim.x*blockDim.x) {
        float v = h5[i] + g_res[i];
        buf[i] = v;
        s  += (double)v;
        s2 += (double)v * (double)v;
    }
    #pragma unroll
    for (int o = 16; o; o >>= 1) {
        s  += __shfl_xor_sync(0xffffffffu, s,  o);
        s2 += __shfl_xor_sync(0xffffffffu, s2, o);
    }
    __shared__ double sh[8], sh2[8];
    int lane = threadIdx.x & 31, wid = threadIdx.x >> 5;
    if (lane == 0) { sh[wid] = s; sh2[wid] = s2; }
    __syncthreads();
    if (wid == 0) {
        int nw = blockDim.x >> 5;
        s  = (lane < nw) ? sh[lane]  : 0.0;
        s2 = (lane < nw) ? sh2[lane] : 0.0;
        #pragma unroll
        for (int o = 4; o; o >>= 1) {
            s  += __shfl_xor_sync(0xffffffffu, s,  o);
            s2 += __shfl_xor_sync(0xffffffffu, s2, o);
        }
        if (lane == 0) { atomicAdd(&g_stat[0], s); atomicAdd(&g_stat[1], s2); }
    }
}

// ---------------- graph LayerNorm + write output ----------------------------
__global__ void k_final(const float* __restrict__ buf, const float* __restrict__ w,
        const float* __restrict__ bb, float* __restrict__ out) {
    double mu  = g_stat[0] / (double)TOT;
    double var = g_stat[1] / (double)TOT - mu*mu;
    float rs  = (float)(1.0 / sqrt(var + 1e-5));
    float fmu = (float)mu;
    for (int i = blockIdx.x*blockDim.x + threadIdx.x; i < TOT;
         i += gridDim.x*blockDim.x) {
        int c = i % DV;
        out[i] = (buf[i] - fmu) * rs * w[c] + bb[c];
    }
}

// ---------------- launch ----------------------------------------------------
extern "C" void kernel_launch(void* const* d_in, const int* in_sizes, int n_in,
                              void* d_out, int out_size) {
    const float* circ     = (const float*)d_in[0];
    const float* x        = (const float*)d_in[1];
    const int*   ei       = (const int*)d_in[2];   // int32 (JAX x64 disabled)
    const float* Wl_first = (const float*)d_in[3];
    const float* Wr_first = (const float*)d_in[4];
    const float* att_first= (const float*)d_in[5];
    const float* b_first  = (const float*)d_in[6];
    const float* Wl_inner = (const float*)d_in[7];
    const float* Wr_inner = (const float*)d_in[8];
    const float* att_inner= (const float*)d_in[9];
    const float* b_inner  = (const float*)d_in[10];
    const float* Wl_last  = (const float*)d_in[11];
    const float* Wr_last  = (const float*)d_in[12];
    const float* att_last = (const float*)d_in[13];
    const float* b_last   = (const float*)d_in[14];
    const float* ln_w     = (const float*)d_in[15];
    const float* ln_b     = (const float*)d_in[16];
    float*       outp     = (float*)d_out;

    float *hA, *hB, *xl, *xr;
    cudaGetSymbolAddress((void**)&hA, g_hA);
    cudaGetSymbolAddress((void**)&hB, g_hB);
    cudaGetSymbolAddress((void**)&xl, g_xl);
    cudaGetSymbolAddress((void**)&xr, g_xr);

    k_init    <<<(NN  + 255)/256, 256>>>();
    k_build_h0<<<(TOT + 255)/256, 256>>>(x, circ);
    k_count   <<<(NE  + 255)/256, 256>>>(ei);
    k_scan    <<<1, 1024>>>();
    k_scatter <<<(NE2 + 255)/256, 256>>>(ei);

    const float* Wls[5]  = {Wl_first, Wl_inner, Wl_inner + 384*384,
                            Wl_inner + 2*384*384, Wl_last};
    const float* Wrs[5]  = {Wr_first, Wr_inner, Wr_inner + 384*384,
                            Wr_inner + 2*384*384, Wr_last};
    const float* atts[5] = {att_first, att_inner, att_inner + 384,
                            att_inner + 2*384, att_last};
    const float* bs[5]   = {b_first, b_inner, b_inner + 384, b_inner + 2*384, b_last};
    int Ks[5] = {96, 384, 384, 384, 384};
    int Hs[5] = {4, 4, 4, 4, 1};

    float* hin  = hA;
    float* hout = hB;
    for (int l = 0; l < 5; l++) {
        int W = Hs[l]*96;
        dim3 gg((W + 63)/64, NN/128);
        k_gemm<<<gg, 256>>>(hin, Wls[l], xl, Ks[l], W);
        k_gemm<<<gg, 256>>>(hin, Wrs[l], xr, Ks[l], W);
        k_logits<<<(NE2*32 + 255)/256, 256>>>(xl, xr, atts[l], Hs[l]);
        k_agg<<<NN, W>>>(xl, bs[l], hout, Hs[l]);
        float* t = hin; hin = hout; hout = t;
    }
    k_resred<<<512, 256>>>(hin, hout);
    k_final <<<(TOT + 255)/256, 256>>>(hout, ln_w, ln_b, outp);
}

// round 3
// speedup vs baseline: 1.2138x; 1.2138x over previous
#include <cuda_runtime.h>
#include <math.h>

#define NN    6912                 // nodes
#define NE    82944                // edges (no self loops)
#define NE2   89856                // edges + self loops
#define DV    96                   // per-node feature width
#define TOT   (NN*DV)              // 663552 output elements
#define HIDW  384

// ---------------- scratch (static device globals; no allocs) ----------------
__device__ __align__(128) float g_hA[NN*HIDW];
__device__ __align__(128) float g_hB[NN*HIDW];
__device__ __align__(128) float g_res[TOT];
__device__ __align__(128) float g_xl[NN*HIDW];
__device__ __align__(128) float g_xr[NN*HIDW];
__device__ __align__(128) float g_logits[NE2*4];
__device__ int    g_off[NN+1];
__device__ int    g_cur[NN];
__device__ int    g_deg[NN];
__device__ int    g_csrc[NE2];
__device__ double g_stat[2];

// ---- h0 = concat(x, repeat(circ,Q)); residual; init deg & LN stats ---------
__global__ void k_build_h0(const float* __restrict__ x, const float* __restrict__ cf) {
    int i = blockIdx.x*blockDim.x + threadIdx.x;
    if (i < NN) g_deg[i] = 1;                       // self loop
    if (i == 0) { g_stat[0] = 0.0; g_stat[1] = 0.0; }
    if (i >= TOT) return;
    int row = i / DV;
    int col = i - row*DV;
    float v;
    if (col < 32) v = x[row*32 + col];
    else          v = cf[(row/27)*64 + (col - 32)];
    g_hA[i]  = v;
    g_res[i] = v;
}

__global__ void k_count(const int* __restrict__ ei) {
    int e = blockIdx.x*blockDim.x + threadIdx.x;
    if (e < NE) atomicAdd(&g_deg[ei[NE + e]], 1);
}

// ---- single-block scan: 1024 thr x 7 elems, warp-scan hierarchy ------------
__global__ void k_scan() {
    __shared__ int wsum[32];
    __shared__ int wbase[32];
    __shared__ int stot;
    int tid = threadIdx.x, lane = tid & 31, wid = tid >> 5;
    int base = tid*7;
    int v[7]; int s = 0;
    #pragma unroll
    for (int j = 0; j < 7; j++) {
        int i = base + j;
        v[j] = (i < NN) ? g_deg[i] : 0;
        s += v[j];
    }
    int incl = s;
    #pragma unroll
    for (int o = 1; o < 32; o <<= 1) {
        int t = __shfl_up_sync(0xffffffffu, incl, o);
        if (lane >= o) incl += t;
    }
    if (lane == 31) wsum[wid] = incl;
    __syncthreads();
    if (wid == 0) {
        int x = wsum[lane];
        int xi = x;
        #pragma unroll
        for (int o = 1; o < 32; o <<= 1) {
            int t = __shfl_up_sync(0xffffffffu, xi, o);
            if (lane >= o) xi += t;
        }
        wbase[lane] = xi - x;
        if (lane == 31) stot = xi;
    }
    __syncthreads();
    int ex = wbase[wid] + (incl - s);
    #pragma unroll
    for (int j = 0; j < 7; j++) {
        int i = base + j;
        if (i < NN) { g_off[i] = ex; g_cur[i] = ex; }
        ex += v[j];
    }
    if (tid == 0) g_off[NN] = stot;
}

__global__ void k_scatter(const int* __restrict__ ei) {
    int i = blockIdx.x*blockDim.x + threadIdx.x;
    if (i >= NE2) return;
    int s, d;
    if (i < NE) { s = ei[i]; d = ei[NE + i]; }
    else        { s = i - NE; d = s; }
    int pos = atomicAdd(&g_cur[d], 1);
    g_csrc[pos] = s;
}

// ---- dual GEMM: C1 = A@B1, C2 = A@B2 (shared A tiles) ----------------------
// 128x64 tile, BK=16, 256 threads, 8x4 per thread per output matrix.
__global__ void __launch_bounds__(256) k_gemm2(const float* __restrict__ A,
        const float* __restrict__ B1, const float* __restrict__ B2,
        float* __restrict__ C1, float* __restrict__ C2, int K, int Nc) {
    __shared__ float As[128][20];       // row-major, padded (80B rows, 16B aligned)
    __shared__ float Bs[2][16][64];
    int tid = threadIdx.x;
    int tx = tid & 15, ty = tid >> 4;
    int bn0 = blockIdx.x * 64;
    int m0  = blockIdx.y * 128;

    int ar0 = tid >> 2, aq = tid & 3;           // A: rows ar0, ar0+64; k-quad aq
    int bk  = tid >> 4, bn4 = (tid & 15) * 4;   // B: k-row bk, n-quad
    bool bok = (bn0 + bn4) < Nc;                // Nc % 4 == 0

    float c1[8][4], c2[8][4];
    #pragma unroll
    for (int i = 0; i < 8; i++)
        #pragma unroll
        for (int j = 0; j < 4; j++) { c1[i][j] = 0.f; c2[i][j] = 0.f; }

    for (int k0 = 0; k0 < K; k0 += 16) {
        #pragma unroll
        for (int l = 0; l < 2; l++) {
            int r = ar0 + l*64;
            float4 v = *(const float4*)(A + (size_t)(m0 + r)*K + k0 + aq*4);
            *(float4*)&As[r][aq*4] = v;
        }
        float4 z = make_float4(0.f, 0.f, 0.f, 0.f);
        float4 b1v = bok ? *(const float4*)(B1 + (size_t)(k0 + bk)*Nc + bn0 + bn4) : z;
        float4 b2v = bok ? *(const float4*)(B2 + (size_t)(k0 + bk)*Nc + bn0 + bn4) : z;
        *(float4*)&Bs[0][bk][bn4] = b1v;
        *(float4*)&Bs[1][bk][bn4] = b2v;
        __syncthreads();
        #pragma unroll
        for (int k = 0; k < 16; k++) {
            float4 q1 = *(float4*)&Bs[0][k][tx*4];
            float4 q2 = *(float4*)&Bs[1][k][tx*4];
            float a[8];
            #pragma unroll
            for (int i = 0; i < 8; i++) a[i] = As[ty*8 + i][k];
            #pragma unroll
            for (int i = 0; i < 8; i++) {
                c1[i][0] = fmaf(a[i], q1.x, c1[i][0]);
                c1[i][1] = fmaf(a[i], q1.y, c1[i][1]);
                c1[i][2] = fmaf(a[i], q1.z, c1[i][2]);
                c1[i][3] = fmaf(a[i], q1.w, c1[i][3]);
                c2[i][0] = fmaf(a[i], q2.x, c2[i][0]);
                c2[i][1] = fmaf(a[i], q2.y, c2[i][1]);
                c2[i][2] = fmaf(a[i], q2.z, c2[i][2]);
                c2[i][3] = fmaf(a[i], q2.w, c2[i][3]);
            }
        }
        __syncthreads();
    }
    int ccol = bn0 + tx*4;
    if (ccol < Nc) {
        #pragma unroll
        for (int i = 0; i < 8; i++) {
            size_t row = (size_t)(m0 + ty*8 + i);
            *(float4*)(C1 + row*Nc + ccol) =
                make_float4(c1[i][0], c1[i][1], c1[i][2], c1[i][3]);
            *(float4*)(C2 + row*Nc + ccol) =
                make_float4(c2[i][0], c2[i][1], c2[i][2], c2[i][3]);
        }
    }
}

// ---- attention logits: block per dst node, xr+att cached in registers ------
// blockDim = 32*H; warp h computes head h's logit for each incident edge.
__global__ void k_logits2(const float* __restrict__ xl, const float* __restrict__ xr,
        const float* __restrict__ att, int H) {
    int b = blockIdx.x;
    int h = threadIdx.x >> 5, lane = threadIdx.x & 31;
    int W = H * 96;
    int c = h*96 + lane;
    float xr0 = xr[(size_t)b*W + c];
    float xr1 = xr[(size_t)b*W + c + 32];
    float xr2 = xr[(size_t)b*W + c + 64];
    float at0 = __ldg(att + c);
    float at1 = __ldg(att + c + 32);
    float at2 = __ldg(att + c + 64);
    int e1 = g_off[b+1];
    for (int e = g_off[b]; e < e1; e++) {
        const float* ps = xl + (size_t)g_csrc[e]*W + h*96;
        float v0 = ps[lane]      + xr0;
        float v1 = ps[lane + 32] + xr1;
        float v2 = ps[lane + 64] + xr2;
        v0 = v0 > 0.f ? v0 : 0.2f*v0;
        v1 = v1 > 0.f ? v1 : 0.2f*v1;
        v2 = v2 > 0.f ? v2 : 0.2f*v2;
        float acc = fmaf(at0, v0, fmaf(at1, v1, at2*v2));
        #pragma unroll
        for (int o = 16; o; o >>= 1) acc += __shfl_xor_sync(0xffffffffu, acc, o);
        if (lane == 0) g_logits[(size_t)e*H + h] = acc;
    }
}

// ---- per-dst softmax + aggregation (block per node, blockDim = H*96) -------
__global__ void k_agg(const float* __restrict__ xl, const float* __restrict__ bias,
        float* __restrict__ out, int H) {
    int b   = blockIdx.x;
    int tid = threadIdx.x;
    int W   = blockDim.x;            // H*96
    int h   = tid / 96;
    int lane = tid & 31, wid = tid >> 5;
    int e0 = g_off[b], deg = g_off[b+1] - e0;

    __shared__ float s_m[4], s_id[4];
    if (wid < H) {
        float m = -1e30f;
        for (int i = lane; i < deg; i += 32)
            m = fmaxf(m, g_logits[(size_t)(e0+i)*H + wid]);
        #pragma unroll
        for (int o = 16; o; o >>= 1) m = fmaxf(m, __shfl_xor_sync(0xffffffffu, m, o));
        float ss = 0.f;
        for (int i = lane; i < deg; i += 32)
            ss += __expf(g_logits[(size_t)(e0+i)*H + wid] - m);
        #pragma unroll
        for (int o = 16; o; o >>= 1) ss += __shfl_xor_sync(0xffffffffu, ss, o);
        if (lane == 0) { s_m[wid] = m; s_id[wid] = 1.f/ss; }
    }
    __syncthreads();

    __shared__ float s_alpha[4*96];
    __shared__ int   s_src[96];
    float a0 = 0.f, a1 = 0.f;
    for (int base = 0; base < deg; base += 96) {
        int cn = min(96, deg - base);
        if (tid < cn) s_src[tid] = g_csrc[e0 + base + tid];
        if (wid < H) {
            float m = s_m[wid], id = s_id[wid];
            for (int i = lane; i < cn; i += 32)
                s_alpha[wid*96 + i] =
                    __expf(g_logits[(size_t)(e0 + base + i)*H + wid] - m) * id;
        }
        __syncthreads();
        int i = 0;
        for (; i + 2 <= cn; i += 2) {
            a0 = fmaf(s_alpha[h*96 + i],     xl[(size_t)s_src[i]  *W + tid], a0);
            a1 = fmaf(s_alpha[h*96 + i + 1], xl[(size_t)s_src[i+1]*W + tid], a1);
        }
        if (i < cn) a0 = fmaf(s_alpha[h*96 + i], xl[(size_t)s_src[i]*W + tid], a0);
        __syncthreads();
    }
    float o = a0 + a1 + bias[tid];
    out[(size_t)b*W + tid] = o > 0.f ? o : 0.01f*o;
}

// ---- residual add + LN statistics ------------------------------------------
__global__ void k_resred(const float* __restrict__ h5, float* __restrict__ buf) {
    double s = 0.0, s2 = 0.0;
    for (int i = blockIdx.x*blockDim.x + threadIdx.x; i < TOT;
         i += gridDim.x*blockDim.x) {
        float v = h5[i] + g_res[i];
        buf[i] = v;
        s  += (double)v;
        s2 += (double)v * (double)v;
    }
    #pragma unroll
    for (int o = 16; o; o >>= 1) {
        s  += __shfl_xor_sync(0xffffffffu, s,  o);
        s2 += __shfl_xor_sync(0xffffffffu, s2, o);
    }
    __shared__ double sh[8], sh2[8];
    int lane = threadIdx.x & 31, wid = threadIdx.x >> 5;
    if (lane == 0) { sh[wid] = s; sh2[wid] = s2; }
    __syncthreads();
    if (wid == 0) {
        int nw = blockDim.x >> 5;
        s  = (lane < nw) ? sh[lane]  : 0.0;
        s2 = (lane < nw) ? sh2[lane] : 0.0;
        #pragma unroll
        for (int o = 4; o; o >>= 1) {
            s  += __shfl_xor_sync(0xffffffffu, s,  o);
            s2 += __shfl_xor_sync(0xffffffffu, s2, o);
        }
        if (lane == 0) { atomicAdd(&g_stat[0], s); atomicAdd(&g_stat[1], s2); }
    }
}

// ---- graph LayerNorm + write output ----------------------------------------
__global__ void k_final(const float* __restrict__ buf, const float* __restrict__ w,
        const float* __restrict__ bb, float* __restrict__ out) {
    double mu  = g_stat[0] / (double)TOT;
    double var = g_stat[1] / (double)TOT - mu*mu;
    float rs  = (float)(1.0 / sqrt(var + 1e-5));
    float fmu = (float)mu;
    for (int i = blockIdx.x*blockDim.x + threadIdx.x; i < TOT;
         i += gridDim.x*blockDim.x) {
        int c = i % DV;
        out[i] = (buf[i] - fmu) * rs * w[c] + bb[c];
    }
}

// ---- launch -----------------------------------------------------------------
extern "C" void kernel_launch(void* const* d_in, const int* in_sizes, int n_in,
                              void* d_out, int out_size) {
    const float* circ     = (const float*)d_in[0];
    const float* x        = (const float*)d_in[1];
    const int*   ei       = (const int*)d_in[2];   // int32 (JAX x64 disabled)
    const float* Wl_first = (const float*)d_in[3];
    const float* Wr_first = (const float*)d_in[4];
    const float* att_first= (const float*)d_in[5];
    const float* b_first  = (const float*)d_in[6];
    const float* Wl_inner = (const float*)d_in[7];
    const float* Wr_inner = (const float*)d_in[8];
    const float* att_inner= (const float*)d_in[9];
    const float* b_inner  = (const float*)d_in[10];
    const float* Wl_last  = (const float*)d_in[11];
    const float* Wr_last  = (const float*)d_in[12];
    const float* att_last = (const float*)d_in[13];
    const float* b_last   = (const float*)d_in[14];
    const float* ln_w     = (const float*)d_in[15];
    const float* ln_b     = (const float*)d_in[16];
    float*       outp     = (float*)d_out;

    float *hA, *hB, *xl, *xr;
    cudaGetSymbolAddress((void**)&hA, g_hA);
    cudaGetSymbolAddress((void**)&hB, g_hB);
    cudaGetSymbolAddress((void**)&xl, g_xl);
    cudaGetSymbolAddress((void**)&xr, g_xr);

    k_build_h0<<<(TOT + 255)/256, 256>>>(x, circ);
    k_count   <<<(NE  + 255)/256, 256>>>(ei);
    k_scan    <<<1, 1024>>>();
    k_scatter <<<(NE2 + 255)/256, 256>>>(ei);

    const float* Wls[5]  = {Wl_first, Wl_inner, Wl_inner + 384*384,
                            Wl_inner + 2*384*384, Wl_last};
    const float* Wrs[5]  = {Wr_first, Wr_inner, Wr_inner + 384*384,
                            Wr_inner + 2*384*384, Wr_last};
    const float* atts[5] = {att_first, att_inner, att_inner + 384,
                            att_inner + 2*384, att_last};
    const float* bs[5]   = {b_first, b_inner, b_inner + 384, b_inner + 2*384, b_last};
    int Ks[5] = {96, 384, 384, 384, 384};
    int Hs[5] = {4, 4, 4, 4, 1};

    float* hin  = hA;
    float* hout = hB;
    for (int l = 0; l < 5; l++) {
        int W = Hs[l]*96;
        dim3 gg((W + 63)/64, NN/128);
        k_gemm2 <<<gg, 256>>>(hin, Wls[l], Wrs[l], xl, xr, Ks[l], W);
        k_logits2<<<NN, 32*Hs[l]>>>(xl, xr, atts[l], Hs[l]);
        k_agg   <<<NN, W>>>(xl, bs[l], hout, Hs[l]);
        float* t = hin; hin = hout; hout = t;
    }
    k_resred<<<512, 256>>>(hin, hout);
    k_final <<<(TOT + 255)/256, 256>>>(hout, ln_w, ln_b, outp);
}

// round 5
// speedup vs baseline: 1.5647x; 1.2891x over previous
#include <cuda_runtime.h>
#include <cuda_bf16.h>
#include <math.h>
#include <stdint.h>

#define NN    6912                 // nodes
#define NE    82944                // edges (no self loops)
#define NE2   89856                // edges + self loops
#define DV    96                   // per-node feature width
#define TOT   (NN*DV)              // 663552 output elements
#define HIDW  384
#define WSLOT (384*384)

// ---------------- scratch (static device globals; no allocs) ----------------
__device__ __align__(128) float g_hA[NN*HIDW];
__device__ __align__(128) float g_hB[NN*HIDW];
__device__ __align__(128) float g_res[TOT];
__device__ __align__(128) float g_xl[NN*HIDW];
__device__ __align__(128) float g_xr[NN*HIDW];
__device__ __align__(128) float g_logits[NE2*4];
__device__ __align__(128) __nv_bfloat16 g_ah[NN*HIDW];
__device__ __align__(128) __nv_bfloat16 g_al[NN*HIDW];
__device__ __align__(128) __nv_bfloat16 g_wbh[10*WSLOT];
__device__ __align__(128) __nv_bfloat16 g_wbl[10*WSLOT];
__device__ int    g_off[NN+1];
__device__ int    g_cur[NN];
__device__ int    g_deg[NN];
__device__ int    g_csrc[NE2];
__device__ double g_stat[2];

// ---- h0 = concat(x, repeat(circ,Q)); residual; init deg & LN stats ---------
__global__ void k_build_h0(const float* __restrict__ x, const float* __restrict__ cf) {
    int i = blockIdx.x*blockDim.x + threadIdx.x;
    if (i < NN) g_deg[i] = 1;
    if (i == 0) { g_stat[0] = 0.0; g_stat[1] = 0.0; }
    if (i >= TOT) return;
    int row = i / DV;
    int col = i - row*DV;
    float v;
    if (col < 32) v = x[row*32 + col];
    else          v = cf[(row/27)*64 + (col - 32)];
    g_hA[i]  = v;
    g_res[i] = v;
}

__global__ void k_count(const int* __restrict__ ei) {
    int e = blockIdx.x*blockDim.x + threadIdx.x;
    if (e < NE) atomicAdd(&g_deg[ei[NE + e]], 1);
}

__global__ void k_scan() {
    __shared__ int wsum[32], wbase[32];
    __shared__ int stot;
    int tid = threadIdx.x, lane = tid & 31, wid = tid >> 5;
    int base = tid*7;
    int v[7]; int s = 0;
    #pragma unroll
    for (int j = 0; j < 7; j++) {
        int i = base + j;
        v[j] = (i < NN) ? g_deg[i] : 0;
        s += v[j];
    }
    int incl = s;
    #pragma unroll
    for (int o = 1; o < 32; o <<= 1) {
        int t = __shfl_up_sync(0xffffffffu, incl, o);
        if (lane >= o) incl += t;
    }
    if (lane == 31) wsum[wid] = incl;
    __syncthreads();
    if (wid == 0) {
        int x = wsum[lane];
        int xi = x;
        #pragma unroll
        for (int o = 1; o < 32; o <<= 1) {
            int t = __shfl_up_sync(0xffffffffu, xi, o);
            if (lane >= o) xi += t;
        }
        wbase[lane] = xi - x;
        if (lane == 31) stot = xi;
    }
    __syncthreads();
    int ex = wbase[wid] + (incl - s);
    #pragma unroll
    for (int j = 0; j < 7; j++) {
        int i = base + j;
        if (i < NN) { g_off[i] = ex; g_cur[i] = ex; }
        ex += v[j];
    }
    if (tid == 0) g_off[NN] = stot;
}

__global__ void k_scatter(const int* __restrict__ ei) {
    int i = blockIdx.x*blockDim.x + threadIdx.x;
    if (i >= NE2) return;
    int s, d;
    if (i < NE) { s = ei[i]; d = ei[NE + i]; }
    else        { s = i - NE; d = s; }
    int pos = atomicAdd(&g_cur[d], 1);
    g_csrc[pos] = s;
}

// ---- weight convert: W[K,Nc] fp32 -> hi/lo bf16 [Nc,Kpad] (transposed) -----
__global__ void k_cvt_w(const float* __restrict__ W, __nv_bfloat16* __restrict__ oh,
        __nv_bfloat16* __restrict__ ol, int K, int Nc, int Kpad) {
    int i = blockIdx.x*blockDim.x + threadIdx.x;
    if (i >= Nc*Kpad) return;
    int n = i / Kpad, k = i - n*Kpad;
    float v = (k < K) ? W[(size_t)k*Nc + n] : 0.f;
    __nv_bfloat16 h = __float2bfloat16(v);
    oh[i] = h;
    ol[i] = __float2bfloat16(v - __bfloat162float(h));
}

// ---- activation convert: A[NN,K] fp32 -> hi/lo bf16 [NN,Kpad] --------------
__global__ void k_cvt_a(const float* __restrict__ A, __nv_bfloat16* __restrict__ oh,
        __nv_bfloat16* __restrict__ ol, int K, int Kpad) {
    int i = blockIdx.x*blockDim.x + threadIdx.x;
    if (i >= NN*Kpad) return;
    int r = i / Kpad, k = i - r*Kpad;
    float v = (k < K) ? A[(size_t)r*K + k] : 0.f;
    __nv_bfloat16 h = __float2bfloat16(v);
    oh[i] = h;
    ol[i] = __float2bfloat16(v - __bfloat162float(h));
}

// ---- mma.sync bf16 split GEMM: C = A @ W^T ---------------------------------
// CTA 256 thr (8 warps, 4m x 2n), tile 128x128, KC=32.
// A [M,Kg] row-major hi/lo; B [Nc,Kg] row-major hi/lo (= col-major operand).
#define KC 32
#define APITCH 40

__device__ __forceinline__ void mma16816(float* c, const uint32_t* a,
                                         uint32_t b0, uint32_t b1) {
    asm volatile(
        "mma.sync.aligned.m16n8k16.row.col.f32.bf16.bf16.f32 "
        "{%0,%1,%2,%3},{%4,%5,%6,%7},{%8,%9},{%0,%1,%2,%3};"
        : "+f"(c[0]), "+f"(c[1]), "+f"(c[2]), "+f"(c[3])
        : "r"(a[0]), "r"(a[1]), "r"(a[2]), "r"(a[3]), "r"(b0), "r"(b1));
}

__global__ void __launch_bounds__(256) k_mmagemm(
        const __nv_bfloat16* __restrict__ Ah, const __nv_bfloat16* __restrict__ Al,
        const __nv_bfloat16* __restrict__ B1h, const __nv_bfloat16* __restrict__ B1l,
        const __nv_bfloat16* __restrict__ B2h, const __nv_bfloat16* __restrict__ B2l,
        float* __restrict__ C1, float* __restrict__ C2,
        int Kg, int Nc, int ntiles) {
    __shared__ __nv_bfloat16 As[2][128*APITCH];
    __shared__ __nv_bfloat16 Bs[2][128*APITCH];
    int tid = threadIdx.x, wid = tid >> 5, lane = tid & 31;
    int mat = blockIdx.x / ntiles;
    int n0  = (blockIdx.x - mat*ntiles) * 128;
    int m0  = blockIdx.y * 128;
    int Nt  = min(128, Nc - n0);
    const __nv_bfloat16* Bh = mat ? B2h : B1h;
    const __nv_bfloat16* Bl = mat ? B2l : B1l;
    float* C = mat ? C2 : C1;
    int warp_m = wid & 3, warp_n = wid >> 2;
    int gid = lane >> 2, tig = lane & 3;

    float acc[2][8][4];
    #pragma unroll
    for (int mt = 0; mt < 2; mt++)
        #pragma unroll
        for (int nt = 0; nt < 8; nt++)
            #pragma unroll
            for (int j = 0; j < 4; j++) acc[mt][nt][j] = 0.f;

    for (int k0 = 0; k0 < Kg; k0 += KC) {
        #pragma unroll
        for (int g = tid; g < 512; g += 256) {
            int r = g >> 2, q = g & 3;
            size_t ga = (size_t)(m0 + r)*Kg + k0 + q*8;
            *(uint4*)&As[0][r*APITCH + q*8] = *(const uint4*)(Ah + ga);
            *(uint4*)&As[1][r*APITCH + q*8] = *(const uint4*)(Al + ga);
            uint4 bh = make_uint4(0u,0u,0u,0u), bl = bh;
            if (n0 + r < Nc) {
                size_t gb = (size_t)(n0 + r)*Kg + k0 + q*8;
                bh = *(const uint4*)(Bh + gb);
                bl = *(const uint4*)(Bl + gb);
            }
            *(uint4*)&Bs[0][r*APITCH + q*8] = bh;
            *(uint4*)&Bs[1][r*APITCH + q*8] = bl;
        }
        __syncthreads();
        #pragma unroll
        for (int ks = 0; ks < 2; ks++) {
            int cb = ks*16 + tig*2;
            uint32_t afr[2][2][4];
            #pragma unroll
            for (int mt = 0; mt < 2; mt++) {
                int r0 = warp_m*32 + mt*16 + gid;
                #pragma unroll
                for (int hl = 0; hl < 2; hl++) {
                    const __nv_bfloat16* bp = &As[hl][0];
                    afr[mt][hl][0] = *(const uint32_t*)&bp[r0*APITCH + cb];
                    afr[mt][hl][1] = *(const uint32_t*)&bp[(r0+8)*APITCH + cb];
                    afr[mt][hl][2] = *(const uint32_t*)&bp[r0*APITCH + cb + 8];
                    afr[mt][hl][3] = *(const uint32_t*)&bp[(r0+8)*APITCH + cb + 8];
                }
            }
            #pragma unroll
            for (int nt = 0; nt < 8; nt++) {
                int n = warp_n*64 + nt*8 + gid;
                uint32_t bh0 = *(const uint32_t*)&Bs[0][n*APITCH + cb];
                uint32_t bh1 = *(const uint32_t*)&Bs[0][n*APITCH + cb + 8];
                uint32_t bl0 = *(const uint32_t*)&Bs[1][n*APITCH + cb];
                uint32_t bl1 = *(const uint32_t*)&Bs[1][n*APITCH + cb + 8];
                #pragma unroll
                for (int mt = 0; mt < 2; mt++) {
                    mma16816(acc[mt][nt], afr[mt][0], bh0, bh1);
                    mma16816(acc[mt][nt], afr[mt][0], bl0, bl1);
                    mma16816(acc[mt][nt], afr[mt][1], bh0, bh1);
                }
            }
        }
        __syncthreads();
    }

    #pragma unroll
    for (int nt = 0; nt < 8; nt++) {
        int nc = warp_n*64 + nt*8;
        if (nc >= Nt) continue;
        int col = n0 + nc + tig*2;
        #pragma unroll
        for (int mt = 0; mt < 2; mt++) {
            int row = m0 + warp_m*32 + mt*16 + gid;
            *(float2*)(C + (size_t)row*Nc + col) =
                make_float2(acc[mt][nt][0], acc[mt][nt][1]);
            *(float2*)(C + (size_t)(row+8)*Nc + col) =
                make_float2(acc[mt][nt][2], acc[mt][nt][3]);
        }
    }
}

// ---- attention logits: block per dst node ----------------------------------
__global__ void k_logits2(const float* __restrict__ xl, const float* __restrict__ xr,
        const float* __restrict__ att, int H) {
    int b = blockIdx.x;
    int h = threadIdx.x >> 5, lane = threadIdx.x & 31;
    int W = H * 96;
    int c = h*96 + lane;
    float xr0 = xr[(size_t)b*W + c];
    float xr1 = xr[(size_t)b*W + c + 32];
    float xr2 = xr[(size_t)b*W + c + 64];
    float at0 = __ldg(att + c);
    float at1 = __ldg(att + c + 32);
    float at2 = __ldg(att + c + 64);
    int e1 = g_off[b+1];
    for (int e = g_off[b]; e < e1; e++) {
        const float* ps = xl + (size_t)g_csrc[e]*W + h*96;
        float v0 = ps[lane]      + xr0;
        float v1 = ps[lane + 32] + xr1;
        float v2 = ps[lane + 64] + xr2;
        v0 = v0 > 0.f ? v0 : 0.2f*v0;
        v1 = v1 > 0.f ? v1 : 0.2f*v1;
        v2 = v2 > 0.f ? v2 : 0.2f*v2;
        float acc = fmaf(at0, v0, fmaf(at1, v1, at2*v2));
        #pragma unroll
        for (int o = 16; o; o >>= 1) acc += __shfl_xor_sync(0xffffffffu, acc, o);
        if (lane == 0) g_logits[(size_t)e*H + h] = acc;
    }
}

// ---- per-dst softmax + aggregation (block per node, blockDim = H*96) -------
__global__ void k_agg(const float* __restrict__ xl, const float* __restrict__ bias,
        float* __restrict__ out, int H) {
    int b   = blockIdx.x;
    int tid = threadIdx.x;
    int W   = blockDim.x;
    int h   = tid / 96;
    int lane = tid & 31, wid = tid >> 5;
    int e0 = g_off[b], deg = g_off[b+1] - e0;

    __shared__ float s_m[4], s_id[4];
    if (wid < H) {
        float m = -1e30f;
        for (int i = lane; i < deg; i += 32)
            m = fmaxf(m, g_logits[(size_t)(e0+i)*H + wid]);
        #pragma unroll
        for (int o = 16; o; o >>= 1) m = fmaxf(m, __shfl_xor_sync(0xffffffffu, m, o));
        float ss = 0.f;
        for (int i = lane; i < deg; i += 32)
            ss += __expf(g_logits[(size_t)(e0+i)*H + wid] - m);
        #pragma unroll
        for (int o = 16; o; o >>= 1) ss += __shfl_xor_sync(0xffffffffu, ss, o);
        if (lane == 0) { s_m[wid] = m; s_id[wid] = 1.f/ss; }
    }
    __syncthreads();

    __shared__ float s_alpha[4*96];
    __shared__ int   s_src[96];
    float a0 = 0.f, a1 = 0.f;
    for (int base = 0; base < deg; base += 96) {
        int cn = min(96, deg - base);
        if (tid < cn) s_src[tid] = g_csrc[e0 + base + tid];
        if (wid < H) {
            float m = s_m[wid], id = s_id[wid];
            for (int i = lane; i < cn; i += 32)
                s_alpha[wid*96 + i] =
                    __expf(g_logits[(size_t)(e0 + base + i)*H + wid] - m) * id;
        }
        __syncthreads();
        int i = 0;
        for (; i + 2 <= cn; i += 2) {
            a0 = fmaf(s_alpha[h*96 + i],     xl[(size_t)s_src[i]  *W + tid], a0);
            a1 = fmaf(s_alpha[h*96 + i + 1], xl[(size_t)s_src[i+1]*W + tid], a1);
        }
        if (i < cn) a0 = fmaf(s_alpha[h*96 + i], xl[(size_t)s_src[i]*W + tid], a0);
        __syncthreads();
    }
    float o = a0 + a1 + bias[tid];
    out[(size_t)b*W + tid] = o > 0.f ? o : 0.01f*o;
}

// ---- residual add + LN statistics ------------------------------------------
__global__ void k_resred(const float* __restrict__ h5, float* __restrict__ buf) {
    double s = 0.0, s2 = 0.0;
    for (int i = blockIdx.x*blockDim.x + threadIdx.x; i < TOT;
         i += gridDim.x*blockDim.x) {
        float v = h5[i] + g_res[i];
        buf[i] = v;
        s  += (double)v;
        s2 += (double)v * (double)v;
    }
    #pragma unroll
    for (int o = 16; o; o >>= 1) {
        s  += __shfl_xor_sync(0xffffffffu, s,  o);
        s2 += __shfl_xor_sync(0xffffffffu, s2, o);
    }
    __shared__ double sh[8], sh2[8];
    int lane = threadIdx.x & 31, wid = threadIdx.x >> 5;
    if (lane == 0) { sh[wid] = s; sh2[wid] = s2; }
    __syncthreads();
    if (wid == 0) {
        int nw = blockDim.x >> 5;
        s  = (lane < nw) ? sh[lane]  : 0.0;
        s2 = (lane < nw) ? sh2[lane] : 0.0;
        #pragma unroll
        for (int o = 4; o; o >>= 1) {
            s  += __shfl_xor_sync(0xffffffffu, s,  o);
            s2 += __shfl_xor_sync(0xffffffffu, s2, o);
        }
        if (lane == 0) { atomicAdd(&g_stat[0], s); atomicAdd(&g_stat[1], s2); }
    }
}

__global__ void k_final(const float* __restrict__ buf, const float* __restrict__ w,
        const float* __restrict__ bb, float* __restrict__ out) {
    double mu  = g_stat[0] / (double)TOT;
    double var = g_stat[1] / (double)TOT - mu*mu;
    float rs  = (float)(1.0 / sqrt(var + 1e-5));
    float fmu = (float)mu;
    for (int i = blockIdx.x*blockDim.x + threadIdx.x; i < TOT;
         i += gridDim.x*blockDim.x) {
        int c = i % DV;
        out[i] = (buf[i] - fmu) * rs * w[c] + bb[c];
    }
}

// ---- launch -----------------------------------------------------------------
extern "C" void kernel_launch(void* const* d_in, const int* in_sizes, int n_in,
                              void* d_out, int out_size) {
    const float* circ     = (const float*)d_in[0];
    const float* x        = (const float*)d_in[1];
    const int*   ei       = (const int*)d_in[2];
    const float* Wl_first = (const float*)d_in[3];
    const float* Wr_first = (const float*)d_in[4];
    const float* att_first= (const float*)d_in[5];
    const float* b_first  = (const float*)d_in[6];
    const float* Wl_inner = (const float*)d_in[7];
    const float* Wr_inner = (const float*)d_in[8];
    const float* att_inner= (const float*)d_in[9];
    const float* b_inner  = (const float*)d_in[10];
    const float* Wl_last  = (const float*)d_in[11];
    const float* Wr_last  = (const float*)d_in[12];
    const float* att_last = (const float*)d_in[13];
    const float* b_last   = (const float*)d_in[14];
    const float* ln_w     = (const float*)d_in[15];
    const float* ln_b     = (const float*)d_in[16];
    float*       outp     = (float*)d_out;

    float *hA, *hB, *xl, *xr;
    __nv_bfloat16 *ah, *al, *wbh, *wbl;
    cudaGetSymbolAddress((void**)&hA,  g_hA);
    cudaGetSymbolAddress((void**)&hB,  g_hB);
    cudaGetSymbolAddress((void**)&xl,  g_xl);
    cudaGetSymbolAddress((void**)&xr,  g_xr);
    cudaGetSymbolAddress((void**)&ah,  g_ah);
    cudaGetSymbolAddress((void**)&al,  g_al);
    cudaGetSymbolAddress((void**)&wbh, g_wbh);
    cudaGetSymbolAddress((void**)&wbl, g_wbl);

    k_build_h0<<<(TOT + 255)/256, 256>>>(x, circ);
    k_count   <<<(NE  + 255)/256, 256>>>(ei);
    k_scan    <<<1, 1024>>>();
    k_scatter <<<(NE2 + 255)/256, 256>>>(ei);

    const float* Wls[5]  = {Wl_first, Wl_inner, Wl_inner + 384*384,
                            Wl_inner + 2*384*384, Wl_last};
    const float* Wrs[5]  = {Wr_first, Wr_inner, Wr_inner + 384*384,
                            Wr_inner + 2*384*384, Wr_last};
    const float* atts[5] = {att_first, att_inner, att_inner + 384,
                            att_inner + 2*384, att_last};
    const float* bs[5]   = {b_first, b_inner, b_inner + 384, b_inner + 2*384, b_last};
    int Ks[5]    = {96, 384, 384, 384, 384};
    int Kpads[5] = {128, 384, 384, 384, 384};
    int Ncs[5]   = {384, 384, 384, 384, 96};
    int Hs[5]    = {4, 4, 4, 4, 1};

    // convert all weights (transposed, padded, hi/lo split)
    for (int l = 0; l < 5; l++) {
        int tot = Ncs[l]*Kpads[l];
        k_cvt_w<<<(tot + 255)/256, 256>>>(Wls[l], wbh + (2*l)*WSLOT,
                                          wbl + (2*l)*WSLOT, Ks[l], Ncs[l], Kpads[l]);
        k_cvt_w<<<(tot + 255)/256, 256>>>(Wrs[l], wbh + (2*l+1)*WSLOT,
                                          wbl + (2*l+1)*WSLOT, Ks[l], Ncs[l], Kpads[l]);
    }

    float* hin  = hA;
    float* hout = hB;
    for (int l = 0; l < 5; l++) {
        int W = Hs[l]*96;
        int ntiles = (Ncs[l] + 127)/128;
        int atot = NN*Kpads[l];
        k_cvt_a<<<(atot + 255)/256, 256>>>(hin, ah, al, Ks[l], Kpads[l]);
        k_mmagemm<<<dim3(ntiles*2, NN/128), 256>>>(
            ah, al,
            wbh + (2*l)*WSLOT,   wbl + (2*l)*WSLOT,
            wbh + (2*l+1)*WSLOT, wbl + (2*l+1)*WSLOT,
            xl, xr, Kpads[l], Ncs[l], ntiles);
        k_logits2<<<NN, 32*Hs[l]>>>(xl, xr, atts[l], Hs[l]);
        k_agg    <<<NN, W>>>(xl, bs[l], hout, Hs[l]);
        float* t = hin; hin = hout; hout = t;
    }
    k_resred<<<512, 256>>>(hin, hout);
    k_final <<<(TOT + 255)/256, 256>>>(hout, ln_w, ln_b, outp);
}